// round 12
// baseline (speedup 1.0000x reference)
#include <cuda_runtime.h>
#include <cuda_bf16.h>
#include <cstdint>

// ---------------------------------------------------------------------------
// Problem constants
// ---------------------------------------------------------------------------
#define BB 16
#define CC 256
#define TT 2048
#define STEPS 12
#define NNEG 15
#define COPIES 16
#define OFFS 16

#define PRED_TOTAL 6225408   // 389088 rows * 16 copies
#define ROW_TOTAL  389088    // sum_i (2032-i) * 16

// input element counts (all distinct -> size-based binding)
#define SZ_Z    8388608      // 16*256*2048
#define SZ_W    786432       // 256*256*12
#define SZ_BIAS 256
#define SZ_NEG  491520       // 16*15*2048

// ---------------------------------------------------------------------------
// Scratch (device globals: allocation-free)
// ---------------------------------------------------------------------------
__device__ float g_zpred[(size_t)STEPS * BB * TT * CC];  // [i][b][t][o]
__device__ float g_wp[STEPS * CC * CC];                  // [i][c_in][c_out]

// ---------------------------------------------------------------------------
// K1: repack weight[c][o][i] -> wp[i][c][o]
// ---------------------------------------------------------------------------
__global__ void k_repack(const float* __restrict__ w) {
    const int v = blockIdx.x * 256 + threadIdx.x;  // 0..786431
    const int i = v >> 16;
    const int rem = v & 65535;
    const int c = rem >> 8;         // input channel (contraction)
    const int o = rem & 255;        // output channel
    g_wp[v] = w[(size_t)(c * CC + o) * STEPS + i];
}

// ---------------------------------------------------------------------------
// K2: stage-1 GEMM (machinery exonerated across two prior variants).
//   z_pred[i][b][t][o] = sum_c z[b][c][t] * W[c][o][i] + bias[o]
// ---------------------------------------------------------------------------
__global__ void __launch_bounds__(256) k_gemm(const float* __restrict__ z,
                                              const float* __restrict__ bias) {
    const int i  = blockIdx.z;
    const int b  = blockIdx.y;
    const int t0 = blockIdx.x * 32;
    const int tid = threadIdx.x;

    __shared__ float zs[256][33];   // [c][tl], padded

    for (int idx = tid; idx < 256 * 32; idx += 256) {
        const int c  = idx >> 5;
        const int tl = idx & 31;
        zs[c][tl] = z[((size_t)b * CC + c) * TT + t0 + tl];
    }
    __syncthreads();

    const int o = tid;
    float acc[32];
#pragma unroll
    for (int tl = 0; tl < 32; ++tl) acc[tl] = 0.f;

    const float* wcol = g_wp + (size_t)i * CC * CC + o;   // stride CC over c
    for (int c = 0; c < 256; ++c) {
        const float wv = wcol[(size_t)c * CC];
#pragma unroll
        for (int tl = 0; tl < 32; ++tl)
            acc[tl] = fmaf(zs[c][tl], wv, acc[tl]);
    }

    const float bv = bias[o];
    for (int tl = 0; tl < 32; ++tl)
        g_zpred[(((size_t)i * BB + b) * TT + (t0 + tl)) * CC + o] = acc[tl] + bv;
}

// ---------------------------------------------------------------------------
// K3 (NAIVE): one thread per output element.  Direct transcription of
//   p[t,b,n] = sum_c z_pred[b,c,t,i] * targets[n,b,c,t+off],  off = i+16
// No warp tricks, no shuffles, no lane ownership.
// ---------------------------------------------------------------------------
__global__ void __launch_bounds__(256) k_prednaive(const int* __restrict__ neg,
                                                   const float* __restrict__ z,
                                                   float* __restrict__ out) {
    const int e = blockIdx.x * 256 + threadIdx.x;   // 0 .. PRED_TOTAL-1
    if (e >= PRED_TOTAL) return;

    const int flat_row = e >> 4;    // e / 16
    const int n        = e & 15;    // copy index

    // find step block: blockstart(i) = 16*(2032*i - i*(i-1)/2) rows
    int i = 0;
#pragma unroll
    for (int s = 1; s < STEPS; ++s)
        if (flat_row >= 16 * (2032 * s - (s * (s - 1)) / 2)) i = s;

    const int local = flat_row - 16 * (2032 * i - (i * (i - 1)) / 2);
    const int t = local >> 4;       // local / 16
    const int b = local & 15;       // local % 16

    const int off = i + OFFS;
    const int tsrc = t + off;       // target time index (< 2048 guaranteed)

    // target vector source: (tb, tq) into z[b'][c][t']
    int idx;
    if (n == 0) idx = b * TT + tsrc;
    else        idx = neg[(size_t)b * (NNEG * TT) + (n - 1) * TT + tsrc];
    const int tb = idx >> 11;       // / 2048
    const int tq = idx & 2047;      // % 2048

    const float* yrow = g_zpred + (((size_t)i * BB + b) * TT + t) * CC; // over o
    const float* zcol = z + (size_t)tb * CC * TT + tq;                  // stride TT over c

    float p = 0.f;
#pragma unroll 8
    for (int c = 0; c < CC; ++c)
        p = fmaf(yrow[c], zcol[(size_t)c * TT], p);

    out[e] = p;
}

// ---------------------------------------------------------------------------
// K4: zero the labels tail
// ---------------------------------------------------------------------------
__global__ void k_zero(float* out, int n0, int n) {
    const int i = blockIdx.x * 256 + threadIdx.x;
    if (i < n) out[n0 + i] = 0.f;
}

// ---------------------------------------------------------------------------
// launch — inputs bound by element count, not position
// ---------------------------------------------------------------------------
extern "C" void kernel_launch(void* const* d_in, const int* in_sizes, int n_in,
                              void* d_out, int out_size) {
    const float* z = nullptr;
    const float* w = nullptr;
    const float* bias = nullptr;
    const int* neg = nullptr;
    for (int i = 0; i < n_in; ++i) {
        switch (in_sizes[i]) {
            case SZ_Z:    z    = (const float*)d_in[i]; break;
            case SZ_W:    w    = (const float*)d_in[i]; break;
            case SZ_BIAS: bias = (const float*)d_in[i]; break;
            case SZ_NEG:  neg  = (const int*)d_in[i];   break;
        }
    }
    float* out = (float*)d_out;

    k_repack<<<(STEPS * CC * CC) / 256, 256>>>(w);
    k_gemm<<<dim3(TT / 32, BB, STEPS), 256>>>(z, bias);
    k_prednaive<<<(PRED_TOTAL + 255) / 256, 256>>>(neg, z, out);

    const int rem = out_size - PRED_TOTAL;
    if (rem > 0) k_zero<<<(rem + 255) / 256, 256>>>(out, PRED_TOTAL, rem);
}

// round 14
// speedup vs baseline: 2.3410x; 2.3410x over previous
#include <cuda_runtime.h>
#include <cuda_bf16.h>
#include <cstdint>

// ---------------------------------------------------------------------------
// Problem constants
// ---------------------------------------------------------------------------
#define BB 16
#define CC 256
#define TT 2048
#define STEPS 12
#define NNEG 15
#define COPIES 16
#define OFFS 16

#define PRED_TOTAL 6225408   // 389088 rows * 16 copies

// input element counts (all distinct -> size-based binding)
#define SZ_Z    8388608      // 16*256*2048
#define SZ_W    786432       // 256*256*12
#define SZ_BIAS 256
#define SZ_NEG  491520       // 16*15*2048

// ---------------------------------------------------------------------------
// Scratch (device globals: allocation-free)
// ---------------------------------------------------------------------------
__device__ float g_zpred[(size_t)STEPS * BB * TT * CC];  // [i][b][t][o]  402 MB
__device__ float g_zt[(size_t)BB * TT * CC];             // [b][t][c]     33.5 MB
__device__ float g_wp[STEPS * CC * CC];                  // [i][c_in][c_out]

// ---------------------------------------------------------------------------
// K0: transpose z[b][c][t] -> zt[b][t][c] (1KB-contiguous target rows)
// ---------------------------------------------------------------------------
__global__ void k_transpose(const float* __restrict__ z) {
    __shared__ float tile[32][33];
    const int b  = blockIdx.z;
    const int t0 = blockIdx.x * 32;
    const int c0 = blockIdx.y * 32;
    const int tx = threadIdx.x, ty = threadIdx.y;  // 32 x 8

    const float* src = z + ((size_t)b * CC + c0) * TT + t0;
#pragma unroll
    for (int j = 0; j < 32; j += 8)
        tile[ty + j][tx] = src[(size_t)(ty + j) * TT + tx];
    __syncthreads();
    float* dst = g_zt + ((size_t)b * TT + t0) * CC + c0;
#pragma unroll
    for (int j = 0; j < 32; j += 8)
        dst[(size_t)(ty + j) * CC + tx] = tile[tx][ty + j];
}

// ---------------------------------------------------------------------------
// K1: repack weight[c][o][i] -> wp[i][c][o]
// ---------------------------------------------------------------------------
__global__ void k_repack(const float* __restrict__ w) {
    const int v = blockIdx.x * 256 + threadIdx.x;  // 0..786431
    const int i = v >> 16;
    const int rem = v & 65535;
    const int c = rem >> 8;
    const int o = rem & 255;
    g_wp[v] = w[(size_t)(c * CC + o) * STEPS + i];
}

// ---------------------------------------------------------------------------
// K2: stage-1 GEMM (unchanged — exonerated by the round-12 exact pass).
//   z_pred[i][b][t][o] = sum_c z[b][c][t] * W[c][o][i] + bias[o]
// ---------------------------------------------------------------------------
__global__ void __launch_bounds__(256) k_gemm(const float* __restrict__ z,
                                              const float* __restrict__ bias) {
    const int i  = blockIdx.z;
    const int b  = blockIdx.y;
    const int t0 = blockIdx.x * 32;
    const int tid = threadIdx.x;

    __shared__ float zs[256][33];   // [c][tl], padded

    for (int idx = tid; idx < 256 * 32; idx += 256) {
        const int c  = idx >> 5;
        const int tl = idx & 31;
        zs[c][tl] = z[((size_t)b * CC + c) * TT + t0 + tl];
    }
    __syncthreads();

    const int o = tid;
    float acc[32];
#pragma unroll
    for (int tl = 0; tl < 32; ++tl) acc[tl] = 0.f;

    const float* wcol = g_wp + (size_t)i * CC * CC + o;   // stride CC over c
    for (int c = 0; c < 256; ++c) {
        const float wv = wcol[(size_t)c * CC];
#pragma unroll
        for (int tl = 0; tl < 32; ++tl)
            acc[tl] = fmaf(zs[c][tl], wv, acc[tl]);
    }

    const float bv = bias[o];
    for (int tl = 0; tl < 32; ++tl)
        g_zpred[(((size_t)i * BB + b) * TT + (t0 + tl)) * CC + o] = acc[tl] + bv;
}

// ---------------------------------------------------------------------------
// K3: stage-2, reuse-optimized.
// Block per (tt, b), 512 threads = 16 warps.  Warp w:
//   - (staging) warps 0..11 copy y-row i=w (g_zpred[i][b][tt-16-i][:]) to smem
//   - (compute) warp w owns copy n=w: gather target row zt[idx] (1KB, once),
//     12 partial dots vs smem y-rows, one butterfly, lane 0 stores 12 outputs.
// ---------------------------------------------------------------------------
__global__ void __launch_bounds__(512) k_pred2(const int* __restrict__ neg,
                                               float* __restrict__ out) {
    const int tt = blockIdx.x;
    const int b  = blockIdx.y;
    if (tt < OFFS) return;
    const int imax = min(STEPS - 1, tt - OFFS);
    const int wid  = threadIdx.x >> 5;
    const int lane = threadIdx.x & 31;

    __shared__ float ys[12][256];

    if (wid < STEPS && wid <= imax) {
        const float4* src = (const float4*)(g_zpred +
            (((size_t)wid * BB + b) * TT + (tt - OFFS - wid)) * CC);
        ((float4*)ys[wid])[lane]      = src[lane];
        ((float4*)ys[wid])[lane + 32] = src[lane + 32];
    }
    __syncthreads();

    // warp wid handles copy n = wid
    const int n = wid;
    int idx;
    if (n == 0) idx = b * TT + tt;
    else        idx = neg[(size_t)b * (NNEG * TT) + (n - 1) * TT + tt];

    const float4* grow = (const float4*)(g_zt + (size_t)idx * CC);
    const float4 ga = grow[lane * 2];
    const float4 gb = grow[lane * 2 + 1];

    float p[12];
#pragma unroll
    for (int i = 0; i < 12; ++i) {
        const float4 ya = ((const float4*)ys[i])[lane * 2];
        const float4 yb = ((const float4*)ys[i])[lane * 2 + 1];
        float s = 0.f;
        s = fmaf(ya.x, ga.x, s); s = fmaf(ya.y, ga.y, s);
        s = fmaf(ya.z, ga.z, s); s = fmaf(ya.w, ga.w, s);
        s = fmaf(yb.x, gb.x, s); s = fmaf(yb.y, gb.y, s);
        s = fmaf(yb.z, gb.z, s); s = fmaf(yb.w, gb.w, s);
        p[i] = s;
    }

#pragma unroll
    for (int ofs = 16; ofs > 0; ofs >>= 1) {
#pragma unroll
        for (int i = 0; i < 12; ++i)
            p[i] += __shfl_xor_sync(0xffffffffu, p[i], ofs);
    }

    if (lane == 0) {
#pragma unroll
        for (int i = 0; i < 12; ++i) {
            if (i <= imax) {
                const int t = tt - OFFS - i;
                const size_t base = (size_t)256 * (2032 * i - (i * (i - 1)) / 2)
                                  + ((size_t)(t * BB + b)) * COPIES + n;
                out[base] = p[i];
            }
        }
    }
}

// ---------------------------------------------------------------------------
// K4: zero the labels tail
// ---------------------------------------------------------------------------
__global__ void k_zero(float* out, int n0, int n) {
    const int i = blockIdx.x * 256 + threadIdx.x;
    if (i < n) out[n0 + i] = 0.f;
}

// ---------------------------------------------------------------------------
// launch — inputs bound by element count, not position
// ---------------------------------------------------------------------------
extern "C" void kernel_launch(void* const* d_in, const int* in_sizes, int n_in,
                              void* d_out, int out_size) {
    const float* z = nullptr;
    const float* w = nullptr;
    const float* bias = nullptr;
    const int* neg = nullptr;
    for (int i = 0; i < n_in; ++i) {
        switch (in_sizes[i]) {
            case SZ_Z:    z    = (const float*)d_in[i]; break;
            case SZ_W:    w    = (const float*)d_in[i]; break;
            case SZ_BIAS: bias = (const float*)d_in[i]; break;
            case SZ_NEG:  neg  = (const int*)d_in[i];   break;
        }
    }
    float* out = (float*)d_out;

    k_transpose<<<dim3(TT / 32, CC / 32, BB), dim3(32, 8)>>>(z);
    k_repack<<<(STEPS * CC * CC) / 256, 256>>>(w);
    k_gemm<<<dim3(TT / 32, BB, STEPS), 256>>>(z, bias);
    k_pred2<<<dim3(TT, BB), 512>>>(neg, out);

    const int rem = out_size - PRED_TOTAL;
    if (rem > 0) k_zero<<<(rem + 255) / 256, 256>>>(out, PRED_TOTAL, rem);
}

// round 15
// speedup vs baseline: 4.8921x; 2.0897x over previous
#include <cuda_runtime.h>
#include <cuda_bf16.h>
#include <cstdint>

// ---------------------------------------------------------------------------
// Problem constants
// ---------------------------------------------------------------------------
#define BB 16
#define CC 256
#define TT 2048
#define STEPS 12
#define NNEG 15
#define COPIES 16
#define OFFS 16

#define PRED_TOTAL 6225408   // 389088 rows * 16 copies

// input element counts (all distinct -> size-based binding)
#define SZ_Z    8388608      // 16*256*2048
#define SZ_W    786432       // 256*256*12
#define SZ_BIAS 256
#define SZ_NEG  491520       // 16*15*2048

// ---------------------------------------------------------------------------
// Scratch (device globals: allocation-free)
// ---------------------------------------------------------------------------
__device__ float g_zpred[(size_t)STEPS * BB * TT * CC];  // [i][b][t][o]  402 MB
__device__ float g_zt[(size_t)BB * TT * CC];             // [b][t][c]     33.5 MB
__device__ float g_wp[STEPS * CC * CC];                  // [i][c_in][c_out]

// ---------------------------------------------------------------------------
// K0: transpose z[b][c][t] -> zt[b][t][c] (1KB-contiguous target rows)
// ---------------------------------------------------------------------------
__global__ void k_transpose(const float* __restrict__ z) {
    __shared__ float tile[32][33];
    const int b  = blockIdx.z;
    const int t0 = blockIdx.x * 32;
    const int c0 = blockIdx.y * 32;
    const int tx = threadIdx.x, ty = threadIdx.y;  // 32 x 8

    const float* src = z + ((size_t)b * CC + c0) * TT + t0;
#pragma unroll
    for (int j = 0; j < 32; j += 8)
        tile[ty + j][tx] = src[(size_t)(ty + j) * TT + tx];
    __syncthreads();
    float* dst = g_zt + ((size_t)b * TT + t0) * CC + c0;
#pragma unroll
    for (int j = 0; j < 32; j += 8)
        dst[(size_t)(ty + j) * CC + tx] = tile[tx][ty + j];
}

// ---------------------------------------------------------------------------
// K1: repack weight[c][o][i] -> wp[i][c][o]
// ---------------------------------------------------------------------------
__global__ void k_repack(const float* __restrict__ w) {
    const int v = blockIdx.x * 256 + threadIdx.x;  // 0..786431
    const int i = v >> 16;
    const int rem = v & 65535;
    const int c = rem >> 8;
    const int o = rem & 255;
    g_wp[v] = w[(size_t)(c * CC + o) * STEPS + i];
}

// ---------------------------------------------------------------------------
// K2: stage-1 GEMM — register-tiled fp32 microtile.
//   z_pred[i][b][t][o] = sum_c z[b][c][t] * W[c][o][i] + bias[o]
// CTA tile 128(t) x 128(o), BK=16, 256 threads, 8x8 per-thread microtile.
// Contraction order (kt outer, k inner, c = 0..255 serial) identical to the
// verified broadcast kernel -> z_pred bit-identical.
// ---------------------------------------------------------------------------
__global__ void __launch_bounds__(256) k_gemm(const float* __restrict__ z,
                                              const float* __restrict__ bias) {
    const int i  = blockIdx.z;
    const int b  = blockIdx.y;
    const int t0 = (blockIdx.x >> 1) * 128;
    const int n0 = (blockIdx.x & 1) * 128;

    __shared__ float As[16][128];   // [c][t_local]
    __shared__ float Bs[16][128];   // [c][o_local]

    const int tid = threadIdx.x;
    const int ty = tid >> 4;        // 0..15 -> t rows,  m0 = ty*8
    const int tx = tid & 15;        // 0..15 -> o cols,  nn0 = tx*8
    const int m0 = ty * 8;
    const int nn0 = tx * 8;

    float acc[8][8];
#pragma unroll
    for (int r = 0; r < 8; ++r)
#pragma unroll
        for (int c = 0; c < 8; ++c) acc[r][c] = 0.f;

    const float* zb  = z + (size_t)b * CC * TT;
    const float* wpi = g_wp + (size_t)i * CC * CC;

    for (int kt = 0; kt < 16; ++kt) {
        // load 16x128 tiles (512 float4 each, 2 per thread)
#pragma unroll
        for (int j = 0; j < 2; ++j) {
            const int f  = tid + j * 256;      // 0..511
            const int k  = f >> 5;             // 0..15
            const int m4 = (f & 31) << 2;      // 0..124
            *(float4*)&As[k][m4] = *(const float4*)(zb + (size_t)(kt * 16 + k) * TT + t0 + m4);
            *(float4*)&Bs[k][m4] = *(const float4*)(wpi + (size_t)(kt * 16 + k) * CC + n0 + m4);
        }
        __syncthreads();

#pragma unroll
        for (int k = 0; k < 16; ++k) {
            float a[8], bb[8];
            *(float4*)&a[0]  = *(const float4*)&As[k][m0];
            *(float4*)&a[4]  = *(const float4*)&As[k][m0 + 4];
            *(float4*)&bb[0] = *(const float4*)&Bs[k][nn0];
            *(float4*)&bb[4] = *(const float4*)&Bs[k][nn0 + 4];
#pragma unroll
            for (int r = 0; r < 8; ++r)
#pragma unroll
                for (int c = 0; c < 8; ++c)
                    acc[r][c] = fmaf(a[r], bb[c], acc[r][c]);
        }
        __syncthreads();
    }

    float bv[8];
#pragma unroll
    for (int c = 0; c < 8; ++c) bv[c] = bias[n0 + nn0 + c];

#pragma unroll
    for (int r = 0; r < 8; ++r) {
        float* dst = g_zpred + ((((size_t)i * BB + b) * TT + (t0 + m0 + r)) * CC + n0 + nn0);
        float4 v0 = make_float4(acc[r][0] + bv[0], acc[r][1] + bv[1],
                                acc[r][2] + bv[2], acc[r][3] + bv[3]);
        float4 v1 = make_float4(acc[r][4] + bv[4], acc[r][5] + bv[5],
                                acc[r][6] + bv[6], acc[r][7] + bv[7]);
        *(float4*)dst = v0;
        *(float4*)(dst + 4) = v1;
    }
}

// ---------------------------------------------------------------------------
// K3: stage-2, reuse-optimized (unchanged — verified at 634us, rel 3e-7).
// ---------------------------------------------------------------------------
__global__ void __launch_bounds__(512) k_pred2(const int* __restrict__ neg,
                                               float* __restrict__ out) {
    const int tt = blockIdx.x;
    const int b  = blockIdx.y;
    if (tt < OFFS) return;
    const int imax = min(STEPS - 1, tt - OFFS);
    const int wid  = threadIdx.x >> 5;
    const int lane = threadIdx.x & 31;

    __shared__ float ys[12][256];

    if (wid < STEPS && wid <= imax) {
        const float4* src = (const float4*)(g_zpred +
            (((size_t)wid * BB + b) * TT + (tt - OFFS - wid)) * CC);
        ((float4*)ys[wid])[lane]      = src[lane];
        ((float4*)ys[wid])[lane + 32] = src[lane + 32];
    }
    __syncthreads();

    const int n = wid;
    int idx;
    if (n == 0) idx = b * TT + tt;
    else        idx = neg[(size_t)b * (NNEG * TT) + (n - 1) * TT + tt];

    const float4* grow = (const float4*)(g_zt + (size_t)idx * CC);
    const float4 ga = grow[lane * 2];
    const float4 gb = grow[lane * 2 + 1];

    float p[12];
#pragma unroll
    for (int i = 0; i < 12; ++i) {
        const float4 ya = ((const float4*)ys[i])[lane * 2];
        const float4 yb = ((const float4*)ys[i])[lane * 2 + 1];
        float s = 0.f;
        s = fmaf(ya.x, ga.x, s); s = fmaf(ya.y, ga.y, s);
        s = fmaf(ya.z, ga.z, s); s = fmaf(ya.w, ga.w, s);
        s = fmaf(yb.x, gb.x, s); s = fmaf(yb.y, gb.y, s);
        s = fmaf(yb.z, gb.z, s); s = fmaf(yb.w, gb.w, s);
        p[i] = s;
    }

#pragma unroll
    for (int ofs = 16; ofs > 0; ofs >>= 1) {
#pragma unroll
        for (int i = 0; i < 12; ++i)
            p[i] += __shfl_xor_sync(0xffffffffu, p[i], ofs);
    }

    if (lane == 0) {
#pragma unroll
        for (int i = 0; i < 12; ++i) {
            if (i <= imax) {
                const int t = tt - OFFS - i;
                const size_t base = (size_t)256 * (2032 * i - (i * (i - 1)) / 2)
                                  + ((size_t)(t * BB + b)) * COPIES + n;
                out[base] = p[i];
            }
        }
    }
}

// ---------------------------------------------------------------------------
// K4: zero the labels tail
// ---------------------------------------------------------------------------
__global__ void k_zero(float* out, int n0, int n) {
    const int i = blockIdx.x * 256 + threadIdx.x;
    if (i < n) out[n0 + i] = 0.f;
}

// ---------------------------------------------------------------------------
// launch — inputs bound by element count, not position
// ---------------------------------------------------------------------------
extern "C" void kernel_launch(void* const* d_in, const int* in_sizes, int n_in,
                              void* d_out, int out_size) {
    const float* z = nullptr;
    const float* w = nullptr;
    const float* bias = nullptr;
    const int* neg = nullptr;
    for (int i = 0; i < n_in; ++i) {
        switch (in_sizes[i]) {
            case SZ_Z:    z    = (const float*)d_in[i]; break;
            case SZ_W:    w    = (const float*)d_in[i]; break;
            case SZ_BIAS: bias = (const float*)d_in[i]; break;
            case SZ_NEG:  neg  = (const int*)d_in[i];   break;
        }
    }
    float* out = (float*)d_out;

    k_transpose<<<dim3(TT / 32, CC / 32, BB), dim3(32, 8)>>>(z);
    k_repack<<<(STEPS * CC * CC) / 256, 256>>>(w);
    k_gemm<<<dim3(32, BB, STEPS), 256>>>(z, bias);
    k_pred2<<<dim3(TT, BB), 512>>>(neg, out);

    const int rem = out_size - PRED_TOTAL;
    if (rem > 0) k_zero<<<(rem + 255) / 256, 256>>>(out, PRED_TOTAL, rem);
}

// round 17
// speedup vs baseline: 12.0960x; 2.4726x over previous
#include <cuda_runtime.h>
#include <cuda_bf16.h>
#include <cstdint>

// ---------------------------------------------------------------------------
// Problem constants
// ---------------------------------------------------------------------------
#define BB 16
#define CC 256
#define TT 2048
#define STEPS 12
#define NNEG 15
#define COPIES 16
#define OFFS 16

#define PRED_TOTAL 6225408   // 389088 rows * 16 copies

// input element counts (all distinct -> size-based binding)
#define SZ_Z    8388608      // 16*256*2048
#define SZ_W    786432       // 256*256*12
#define SZ_BIAS 256
#define SZ_NEG  491520       // 16*15*2048

// ---------------------------------------------------------------------------
// Scratch (device globals: allocation-free)
// ---------------------------------------------------------------------------
__device__ float g_zpred[(size_t)STEPS * BB * TT * CC];  // [i][b][t][o]  402 MB
__device__ float g_zt[(size_t)BB * TT * CC];             // [b][t][c]     33.5 MB
__device__ float g_wp[STEPS * CC * CC];                  // [i][c_in][c_out], tf32-rounded

__device__ __forceinline__ float tf32r(float x) {
    uint32_t u;
    asm("cvt.rna.tf32.f32 %0, %1;" : "=r"(u) : "f"(x));
    return __uint_as_float(u);
}

__device__ __forceinline__ void mma_tf32(float c[4], const uint32_t a[4], const uint32_t b[2]) {
    asm volatile(
        "mma.sync.aligned.m16n8k8.row.col.f32.tf32.tf32.f32 "
        "{%0,%1,%2,%3}, {%4,%5,%6,%7}, {%8,%9}, {%0,%1,%2,%3};\n"
        : "+f"(c[0]), "+f"(c[1]), "+f"(c[2]), "+f"(c[3])
        : "r"(a[0]), "r"(a[1]), "r"(a[2]), "r"(a[3]), "r"(b[0]), "r"(b[1]));
}

// ---------------------------------------------------------------------------
// K0: transpose z[b][c][t] -> zt[b][t][c] (1KB-contiguous target rows)
// ---------------------------------------------------------------------------
__global__ void k_transpose(const float* __restrict__ z) {
    __shared__ float tile[32][33];
    const int b  = blockIdx.z;
    const int t0 = blockIdx.x * 32;
    const int c0 = blockIdx.y * 32;
    const int tx = threadIdx.x, ty = threadIdx.y;  // 32 x 8

    const float* src = z + ((size_t)b * CC + c0) * TT + t0;
#pragma unroll
    for (int j = 0; j < 32; j += 8)
        tile[ty + j][tx] = src[(size_t)(ty + j) * TT + tx];
    __syncthreads();
    float* dst = g_zt + ((size_t)b * TT + t0) * CC + c0;
#pragma unroll
    for (int j = 0; j < 32; j += 8)
        dst[(size_t)(ty + j) * CC + tx] = tile[tx][ty + j];
}

// ---------------------------------------------------------------------------
// K1: repack weight[c][o][i] -> wp[i][c][o], rounded to tf32
// ---------------------------------------------------------------------------
__global__ void k_repack(const float* __restrict__ w) {
    const int v = blockIdx.x * 256 + threadIdx.x;  // 0..786431
    const int i = v >> 16;
    const int rem = v & 65535;
    const int c = rem >> 8;
    const int o = rem & 255;
    g_wp[v] = tf32r(w[(size_t)(c * CC + o) * STEPS + i]);
}

// ---------------------------------------------------------------------------
// K2: stage-1 GEMM — TF32 tensor cores.
//   z_pred[i][b][t][o] = sum_c z[b][c][t] * W[c][o][i] + bias[o]
// CTA tile 128(t) x 128(o), BK=32, 256 threads (8 warps, 4x2), warp tile
// 32t x 64o = 2 x 8 m16n8k8 fragments.
// ---------------------------------------------------------------------------
__global__ void __launch_bounds__(256) k_gemm(const float* __restrict__ z,
                                              const float* __restrict__ bias) {
    const int i  = blockIdx.z;
    const int b  = blockIdx.y;
    const int t0 = (blockIdx.x >> 1) * 128;
    const int n0 = (blockIdx.x & 1) * 128;

    __shared__ float As[32][136];   // [c][t_local], pad 8 -> conflict-free frags
    __shared__ float Bs[32][136];   // [c][o_local]

    const int tid  = threadIdx.x;
    const int lane = tid & 31;
    const int warp = tid >> 5;
    const int wm = warp >> 1;       // 0..3  (32 t-rows each)
    const int wn = warp & 1;        // 0..1  (64 o-cols each)
    const int gid = lane >> 2;      // 0..7
    const int tg  = lane & 3;       // 0..3

    float acc[2][8][4];
#pragma unroll
    for (int a = 0; a < 2; ++a)
#pragma unroll
        for (int c = 0; c < 8; ++c)
#pragma unroll
            for (int d = 0; d < 4; ++d) acc[a][c][d] = 0.f;

    const float* zb  = z + (size_t)b * CC * TT;
    const float* wpi = g_wp + (size_t)i * CC * CC;

    for (int kt = 0; kt < 8; ++kt) {
#pragma unroll
        for (int j = 0; j < 4; ++j) {
            const int f  = tid + j * 256;      // 0..1023
            const int k  = f >> 5;             // 0..31
            const int m4 = (f & 31) << 2;      // 0..124
            float4 a = *(const float4*)(zb + (size_t)(kt * 32 + k) * TT + t0 + m4);
            float4 ar;
            ar.x = tf32r(a.x); ar.y = tf32r(a.y); ar.z = tf32r(a.z); ar.w = tf32r(a.w);
            *(float4*)&As[k][m4] = ar;
            *(float4*)&Bs[k][m4] = *(const float4*)(wpi + (size_t)(kt * 32 + k) * CC + n0 + m4);
        }
        __syncthreads();

#pragma unroll
        for (int ks = 0; ks < 4; ++ks) {
            const int k0 = ks * 8;
            uint32_t afr[2][4];
            uint32_t bfr[8][2];
#pragma unroll
            for (int mf = 0; mf < 2; ++mf) {
                const int r = wm * 32 + mf * 16 + gid;
                afr[mf][0] = __float_as_uint(As[k0 + tg][r]);
                afr[mf][1] = __float_as_uint(As[k0 + tg][r + 8]);
                afr[mf][2] = __float_as_uint(As[k0 + tg + 4][r]);
                afr[mf][3] = __float_as_uint(As[k0 + tg + 4][r + 8]);
            }
#pragma unroll
            for (int nf = 0; nf < 8; ++nf) {
                const int c = wn * 64 + nf * 8 + gid;
                bfr[nf][0] = __float_as_uint(Bs[k0 + tg][c]);
                bfr[nf][1] = __float_as_uint(Bs[k0 + tg + 4][c]);
            }
#pragma unroll
            for (int mf = 0; mf < 2; ++mf)
#pragma unroll
                for (int nf = 0; nf < 8; ++nf)
                    mma_tf32(acc[mf][nf], afr[mf], bfr[nf]);
        }
        __syncthreads();
    }

#pragma unroll
    for (int mf = 0; mf < 2; ++mf) {
#pragma unroll
        for (int nf = 0; nf < 8; ++nf) {
            const int m = t0 + wm * 32 + mf * 16 + gid;
            const int n = n0 + wn * 64 + nf * 8 + 2 * tg;
            const float bx = bias[n];
            const float by = bias[n + 1];
            float* dst = g_zpred + ((((size_t)i * BB + b) * TT + m) * CC + n);
            *(float2*)dst = make_float2(acc[mf][nf][0] + bx, acc[mf][nf][1] + by);
            float* dst2 = dst + (size_t)8 * CC;
            *(float2*)dst2 = make_float2(acc[mf][nf][2] + bx, acc[mf][nf][3] + by);
        }
    }
}

// ---------------------------------------------------------------------------
// K3: stage-2 v2.  Block per (tt, b), 128 threads = 4 warps.
// Warp w owns copies n = 4w..4w+3 (g rows in registers, coalesced float4).
// y rows staged to smem once; per i: 2 contiguous LDS.128, 4x8 FMA vs g.
// Butterfly-reduce 48 sums; lane i stores float4 (4 copies) for step i.
// ---------------------------------------------------------------------------
__global__ void __launch_bounds__(128) k_pred2(const int* __restrict__ neg,
                                               float* __restrict__ out) {
    const int tt = blockIdx.x;
    const int b  = blockIdx.y;
    if (tt < OFFS) return;
    const int imax = min(STEPS - 1, tt - OFFS);
    const int tid  = threadIdx.x;
    const int wid  = tid >> 5;
    const int lane = tid & 31;

    __shared__ float ys[12][256];
    float4* ys4 = (float4*)ys;

    // stage y rows (each zpred row read exactly once per block)
    for (int f = tid; f < 768; f += 128) {
        const int i  = f >> 6;          // 0..11
        const int c4 = f & 63;          // float4 col
        if (i <= imax) {
            const float4* src = (const float4*)(g_zpred +
                (((size_t)i * BB + b) * TT + (tt - OFFS - i)) * CC);
            ys4[i * 64 + c4] = src[c4];
        }
    }
    __syncthreads();

    // gather 4 target rows into registers (coalesced: lane, lane+32)
    float4 ga[4], gb[4];
#pragma unroll
    for (int cp = 0; cp < 4; ++cp) {
        const int n = wid * 4 + cp;
        int idx;
        if (n == 0) idx = b * TT + tt;
        else        idx = neg[(size_t)b * (NNEG * TT) + (n - 1) * TT + tt];
        const float4* grow = (const float4*)(g_zt + (size_t)idx * CC);
        ga[cp] = grow[lane];
        gb[cp] = grow[lane + 32];
    }

    float p[4][12];
#pragma unroll
    for (int i = 0; i < 12; ++i) {
        const float4 ya = ys4[i * 64 + lane];
        const float4 yb = ys4[i * 64 + 32 + lane];
#pragma unroll
        for (int cp = 0; cp < 4; ++cp) {
            float s = 0.f;
            s = fmaf(ya.x, ga[cp].x, s); s = fmaf(ya.y, ga[cp].y, s);
            s = fmaf(ya.z, ga[cp].z, s); s = fmaf(ya.w, ga[cp].w, s);
            s = fmaf(yb.x, gb[cp].x, s); s = fmaf(yb.y, gb[cp].y, s);
            s = fmaf(yb.z, gb[cp].z, s); s = fmaf(yb.w, gb[cp].w, s);
            p[cp][i] = s;
        }
    }

#pragma unroll
    for (int ofs = 16; ofs > 0; ofs >>= 1)
#pragma unroll
        for (int cp = 0; cp < 4; ++cp)
#pragma unroll
            for (int i = 0; i < 12; ++i)
                p[cp][i] += __shfl_xor_sync(0xffffffffu, p[cp][i], ofs);

    // lane i stores step i's 4 copies (float4, 16B-aligned: base + 4w % 4 == 0)
    float4 res = make_float4(0.f, 0.f, 0.f, 0.f);
#pragma unroll
    for (int i = 0; i < 12; ++i)
        if (lane == i)
            res = make_float4(p[0][i], p[1][i], p[2][i], p[3][i]);

    if (lane <= imax && lane < 12) {
        const int i = lane;
        const int t = tt - OFFS - i;
        const size_t base = (size_t)256 * (2032 * i - (i * (i - 1)) / 2)
                          + ((size_t)(t * BB + b)) * COPIES + wid * 4;
        *(float4*)(out + base) = res;
    }
}

// ---------------------------------------------------------------------------
// K4: zero the labels tail
// ---------------------------------------------------------------------------
__global__ void k_zero(float* out, int n0, int n) {
    const int i = blockIdx.x * 256 + threadIdx.x;
    if (i < n) out[n0 + i] = 0.f;
}

// ---------------------------------------------------------------------------
// launch — inputs bound by element count, not position
// ---------------------------------------------------------------------------
extern "C" void kernel_launch(void* const* d_in, const int* in_sizes, int n_in,
                              void* d_out, int out_size) {
    const float* z = nullptr;
    const float* w = nullptr;
    const float* bias = nullptr;
    const int* neg = nullptr;
    for (int i = 0; i < n_in; ++i) {
        switch (in_sizes[i]) {
            case SZ_Z:    z    = (const float*)d_in[i]; break;
            case SZ_W:    w    = (const float*)d_in[i]; break;
            case SZ_BIAS: bias = (const float*)d_in[i]; break;
            case SZ_NEG:  neg  = (const int*)d_in[i];   break;
        }
    }
    float* out = (float*)d_out;

    k_transpose<<<dim3(TT / 32, CC / 32, BB), dim3(32, 8)>>>(z);
    k_repack<<<(STEPS * CC * CC) / 256, 256>>>(w);
    k_gemm<<<dim3(32, BB, STEPS), 256>>>(z, bias);
    k_pred2<<<dim3(TT, BB), 128>>>(neg, out);

    const int rem = out_size - PRED_TOTAL;
    if (rem > 0) k_zero<<<(rem + 255) / 256, 256>>>(out, PRED_TOTAL, rem);
}